// round 10
// baseline (speedup 1.0000x reference)
#include <cuda_runtime.h>
#include <cuda_bf16.h>

#define BB 4
#define CC 64
#define HH 128
#define WW 128
#define LL 4
#define NOFF 18
#define SV 36   // V row stride in u32 (144B, 16B-aligned rows for ldmatrix)

// ---------------- scratch ----------------
__device__ float g_xnhwc[BB*HH*WW*CC];
__device__ float g_curN [BB*HH*WW*CC];
__device__ float g_dcP  [2][BB*HH*WW*CC];    // ping-pong deform outputs
__device__ float g_feats[LL][BB*HH*WW*CC];
__device__ float g_sum  [LL][BB*CC];
__device__ float g_gates[LL][BB*CC];
__device__ unsigned g_cnt[LL];
__device__ float g_wcumT[64*64*4];           // [j][o] float4 cumulative fuse weights
__device__ uint4 g_WdF[LL*9*1024];           // deform W fragments
__device__ uint4 g_WoF[LL*9*512];            // offset W fragments

// Dekker split of 2 floats into bf16x2 hi + bf16x2 lo (exact residual)
__device__ __forceinline__ void split2(float v0, float v1, unsigned& hi, unsigned& lo) {
    unsigned h;
    asm("cvt.rn.bf16x2.f32 %0, %1, %2;" : "=r"(h) : "f"(v1), "f"(v0));
    float h0 = __uint_as_float(h << 16);
    float h1 = __uint_as_float(h & 0xffff0000u);
    float r0 = v0 - h0, r1 = v1 - h1;
    unsigned l;
    asm("cvt.rn.bf16x2.f32 %0, %1, %2;" : "=r"(l) : "f"(r1), "f"(r0));
    hi = h; lo = l;
}

__device__ __forceinline__ void mma_bf16(float c[4], const unsigned a[4], const unsigned b[2]) {
    asm volatile("mma.sync.aligned.m16n8k16.row.col.f32.bf16.bf16.f32 "
        "{%0,%1,%2,%3}, {%4,%5,%6,%7}, {%8,%9}, {%0,%1,%2,%3};"
        : "+f"(c[0]), "+f"(c[1]), "+f"(c[2]), "+f"(c[3])
        : "r"(a[0]), "r"(a[1]), "r"(a[2]), "r"(a[3]), "r"(b[0]), "r"(b[1]));
}
__device__ __forceinline__ void ldsm4(unsigned r[4], const unsigned* ptr) {
    unsigned addr = (unsigned)__cvta_generic_to_shared(ptr);
    asm volatile("ldmatrix.sync.aligned.m8n8.x4.shared.b16 {%0,%1,%2,%3}, [%4];"
        : "=r"(r[0]), "=r"(r[1]), "=r"(r[2]), "=r"(r[3]) : "r"(addr));
}

// ---------------- prep: fragment-ordered weights + cumulative fuse ----------
__global__ void prep_k(const float* __restrict__ off_w,
                       const float* __restrict__ dc_w,
                       const float* __restrict__ fuse_w)
{
    int i = blockIdx.x * blockDim.x + threadIdx.x;
    if (i < LL*9*4*2*4*32) {            // deform fragments
        int lane = i & 31; int r = i >> 5;
        int nb = r & 3; r >>= 2; int wn = r & 1; r >>= 1;
        int ks = r & 3; r >>= 2; int tap = r % 9; int l = r / 9;
        int t4 = lane & 3, l4 = lane >> 2;
        int o = wn*32 + nb*8 + l4;
        int c2a = ks*8 + t4, c2b = c2a + 4;
        float va0 = dc_w[((l*CC + o)*CC + 2*c2a)*9 + tap];
        float va1 = dc_w[((l*CC + o)*CC + 2*c2a + 1)*9 + tap];
        float vb0 = dc_w[((l*CC + o)*CC + 2*c2b)*9 + tap];
        float vb1 = dc_w[((l*CC + o)*CC + 2*c2b + 1)*9 + tap];
        unsigned ha, la, hb, lb;
        split2(va0, va1, ha, la); split2(vb0, vb1, hb, lb);
        g_WdF[(size_t)(l*9 + tap)*1024 + ((ks*2 + wn)*4 + nb)*32 + lane] = make_uint4(ha, hb, la, lb);
    }
    if (i < LL*9*4*2*2*32) {            // offset fragments (padded outputs)
        int lane = i & 31; int r = i >> 5;
        int nb = r & 1; r >>= 1; int wn = r & 1; r >>= 1;
        int ks = r & 3; r >>= 2; int tap = r % 9; int l = r / 9;
        int t4 = lane & 3, l4 = lane >> 2;
        int o = wn*16 + nb*8 + l4;
        int c2a = ks*8 + t4, c2b = c2a + 4;
        float va0 = 0.f, va1 = 0.f, vb0 = 0.f, vb1 = 0.f;
        if (o < NOFF) {
            va0 = off_w[((l*NOFF + o)*CC + 2*c2a)*9 + tap];
            va1 = off_w[((l*NOFF + o)*CC + 2*c2a + 1)*9 + tap];
            vb0 = off_w[((l*NOFF + o)*CC + 2*c2b)*9 + tap];
            vb1 = off_w[((l*NOFF + o)*CC + 2*c2b + 1)*9 + tap];
        }
        unsigned ha, la, hb, lb;
        split2(va0, va1, ha, la); split2(vb0, vb1, hb, lb);
        g_WoF[(size_t)(l*9 + tap)*512 + ((ks*2 + wn)*2 + nb)*32 + lane] = make_uint4(ha, hb, la, lb);
    }
    if (i < 64*64*4) {                  // wcumT[(j*64+o)*4+t]
        int t = i & 3; int o = (i >> 2) & 63; int j = i >> 8;
        int e = j*4 + t; int lev = e >> 6; int c = e & 63;
        float s = 0.f;
        for (int u = 0; u <= lev; u++) s += fuse_w[o*(LL*CC) + u*CC + c];
        g_wcumT[i] = s;
    }
    if (i < LL*BB*CC) ((float*)g_sum)[i] = 0.f;
    if (i < LL) g_cnt[i] = 0u;
}

// ---------------- NCHW -> NHWC (smem-tiled transpose) ----------------
__global__ void to_nhwc_k(const float* __restrict__ x)
{
    __shared__ float t[64][33];
    int blk = blockIdx.x;
    int xt = blk & 3; int r = blk >> 2; int y = r & 127; int b = r >> 7;
    int x0 = xt * 32;
    int tid = threadIdx.x;              // 256
    int xx = tid & 31, cg = tid >> 5;
    #pragma unroll
    for (int pass = 0; pass < 8; pass++) {
        int c = pass*8 + cg;
        t[c][xx] = x[((size_t)(b*CC + c)*HH + y)*WW + x0 + xx];
    }
    __syncthreads();
    int c = tid & 63, xg = tid >> 6;
    #pragma unroll
    for (int pass = 0; pass < 8; pass++) {
        int xo = pass*4 + xg;
        g_xnhwc[((size_t)((b*HH + y)*WW) + x0 + xo)*CC + c] = t[c][xo];
    }
}

// ---------------- FUSED offset-conv + deform-conv, 64 px/block ---------------
// Last-finishing block also computes the SE gates for this level.
__global__ void __launch_bounds__(256, 3) conv_fused_k(
    const float* __restrict__ off_b, const float* __restrict__ dc_b,
    const float* __restrict__ se_w1, const float* __restrict__ se_b1,
    const float* __restrict__ se_w2, const float* __restrict__ se_b2,
    int lvl, int h, int w, int use_x, int buf)
{
    extern __shared__ unsigned smem[];
    unsigned* Vh[2] = { smem, smem + 2304 };
    unsigned* Vl[2] = { smem + 4608, smem + 6912 };
    float*  s_offm = (float*)(smem + 9216);    // [64][18]
    int*    s_po   = (int*)(smem + 10368);     // 576 ints  (phase 1, overlaps s_mo4)
    int4*   s_mo4  = (int4*)(smem + 10368);    // 576 int4  (phase 2)
    float4* s_mw4  = (float4*)(smem + 12672);  // 576 float4
    __shared__ float sred[64];

    int tid = threadIdx.x;
    int lane = tid & 31, warp = tid >> 5;
    int wm = warp & 3, wn = warp >> 2;
    int t4 = lane & 3, l4 = lane >> 2;
    int pbase = blockIdx.x * 64;
    const float* src = use_x ? g_xnhwc : g_curN;
    float* gdc = g_dcP[buf];
    int hw = h * w;
    int b = pbase / hw;
    const float* sb0 = src + (size_t)b*hw*CC;
    int c4 = lane & 15, pxo = lane >> 4;

    if (tid < 64) sred[tid] = 0.f;

    unsigned lmoff = (unsigned)((wm*16 + (lane & 15))*SV + (lane >> 4)*4);

    // phase-1 metadata: per (px,tap) patch offset (or -1)
    for (int t = tid; t < 576; t += 256) {
        int px = t / 9, k = t - px*9;
        int p = pbase + px;
        int x = p % w; int y = (p / w) % h;
        int yy = y + k/3 - 1, xx = x + k%3 - 1;
        s_po[t] = ((unsigned)yy < (unsigned)h && (unsigned)xx < (unsigned)w)
                    ? (yy*w + xx)*CC : -1;
    }
    __syncthreads();

    #define STAGE_P(tap_, buf_) {                                                 \
        for (int step = 0; step < 4; step++) {                                    \
            int px = step*16 + warp*2 + pxo;                                      \
            int o = s_po[px*9 + (tap_)];                                          \
            float v0 = 0.f, v1 = 0.f, v2 = 0.f, v3 = 0.f;                         \
            if (o >= 0) {                                                         \
                float4 q = *(const float4*)(sb0 + o + 4*c4);                      \
                v0 = q.x; v1 = q.y; v2 = q.z; v3 = q.w;                           \
            }                                                                     \
            unsigned h0, l0, h1, l1;                                              \
            split2(v0, v1, h0, l0); split2(v2, v3, h1, l1);                       \
            *(uint2*)&Vh[buf_][px*SV + 2*c4] = make_uint2(h0, h1);                \
            *(uint2*)&Vl[buf_][px*SV + 2*c4] = make_uint2(l0, l1);                \
        }                                                                         \
    }
    #define STAGE_D(tap_, buf_) {                                                 \
        for (int step = 0; step < 4; step++) {                                    \
            int px = step*16 + warp*2 + pxo;                                      \
            int mt = px*9 + (tap_);                                               \
            int4 mo = s_mo4[mt]; float4 mw = s_mw4[mt];                           \
            const float* sb = sb0 + 4*c4;                                         \
            float v0 = 0.f, v1 = 0.f, v2 = 0.f, v3 = 0.f;                         \
            if (mo.x >= 0) { float4 q = *(const float4*)(sb + mo.x); v0 += mw.x*q.x; v1 += mw.x*q.y; v2 += mw.x*q.z; v3 += mw.x*q.w; } \
            if (mo.y >= 0) { float4 q = *(const float4*)(sb + mo.y); v0 += mw.y*q.x; v1 += mw.y*q.y; v2 += mw.y*q.z; v3 += mw.y*q.w; } \
            if (mo.z >= 0) { float4 q = *(const float4*)(sb + mo.z); v0 += mw.z*q.x; v1 += mw.z*q.y; v2 += mw.z*q.z; v3 += mw.z*q.w; } \
            if (mo.w >= 0) { float4 q = *(const float4*)(sb + mo.w); v0 += mw.w*q.x; v1 += mw.w*q.y; v2 += mw.w*q.z; v3 += mw.w*q.w; } \
            unsigned h0, l0, h1, l1;                                              \
            split2(v0, v1, h0, l0); split2(v2, v3, h1, l1);                       \
            *(uint2*)&Vh[buf_][px*SV + 2*c4] = make_uint2(h0, h1);                \
            *(uint2*)&Vl[buf_][px*SV + 2*c4] = make_uint2(l0, l1);                \
        }                                                                         \
    }

    // ============ PHASE 1: offset conv (NB=2) ============
    {
        float acc[2][4];
        #pragma unroll
        for (int n = 0; n < 2; n++)
            #pragma unroll
            for (int q = 0; q < 4; q++) acc[n][q] = 0.f;

        const uint4* __restrict__ Wlvl = g_WoF + (size_t)lvl*9*512;
        STAGE_P(0, 0);
        __syncthreads();
        for (int tap = 0; tap < 9; tap++) {
            int cur = tap & 1, nxt = cur ^ 1;
            if (tap < 8) STAGE_P(tap + 1, nxt);
            const unsigned* vh = Vh[cur];
            const unsigned* vl = Vl[cur];
            const uint4* Wp = Wlvl + (size_t)tap*512 + wn*2*32 + lane;
            #pragma unroll
            for (int ks = 0; ks < 4; ks++) {
                unsigned ahi[4], alo[4];
                ldsm4(ahi, vh + lmoff + ks*8);
                ldsm4(alo, vl + lmoff + ks*8);
                #pragma unroll
                for (int nb = 0; nb < 2; nb++) {
                    uint4 wv = __ldg(Wp + (ks*4 + nb)*32);
                    unsigned bhi[2] = { wv.x, wv.y };
                    unsigned blo[2] = { wv.z, wv.w };
                    mma_bf16(acc[nb], ahi, bhi);
                    mma_bf16(acc[nb], alo, bhi);
                    mma_bf16(acc[nb], ahi, blo);
                }
            }
            __syncthreads();
        }
        // write offsets to smem
        int px0l = wm*16 + l4;
        #pragma unroll
        for (int nb = 0; nb < 2; nb++) {
            int o = wn*16 + nb*8 + 2*t4;
            if (o < NOFF) {
                float b0 = off_b[lvl*NOFF + o];
                s_offm[px0l*18 + o]     = acc[nb][0] + b0;
                s_offm[(px0l+8)*18 + o] = acc[nb][2] + b0;
            }
            if (o + 1 < NOFF) {
                float b1 = off_b[lvl*NOFF + o + 1];
                s_offm[px0l*18 + o + 1]     = acc[nb][1] + b1;
                s_offm[(px0l+8)*18 + o + 1] = acc[nb][3] + b1;
            }
        }
        __syncthreads();
    }

    // ============ phase-2 metadata: corner offsets + bilinear weights ============
    for (int t = tid; t < 576; t += 256) {
        int px = t / 9, k = t - px*9;
        int p = pbase + px;
        int x = p % w; int y = (p / w) % h;
        float dy = s_offm[px*18 + 2*k];
        float dx = s_offm[px*18 + 2*k + 1];
        float py  = (float)(y + k/3 - 1) + dy;
        float pxx = (float)(x + k%3 - 1) + dx;
        float y0f = floorf(py), x0f = floorf(pxx);
        int y0 = (int)y0f, x0 = (int)x0f;
        float wy = py - y0f, wx = pxx - x0f;
        bool yi0 = (unsigned)y0       < (unsigned)h;
        bool yi1 = (unsigned)(y0 + 1) < (unsigned)h;
        bool xi0 = (unsigned)x0       < (unsigned)w;
        bool xi1 = (unsigned)(x0 + 1) < (unsigned)w;
        int4 mo; float4 mw;
        mo.x = (yi0 && xi0) ? (y0*w + x0)*CC       : -1;  mw.x = (1.f-wy)*(1.f-wx);
        mo.y = (yi0 && xi1) ? (y0*w + x0 + 1)*CC   : -1;  mw.y = (1.f-wy)*wx;
        mo.z = (yi1 && xi0) ? ((y0+1)*w + x0)*CC   : -1;  mw.z = wy*(1.f-wx);
        mo.w = (yi1 && xi1) ? ((y0+1)*w + x0+1)*CC : -1;  mw.w = wy*wx;
        s_mo4[t] = mo; s_mw4[t] = mw;
    }
    __syncthreads();

    // ============ PHASE 2: deform conv (NB=4) ============
    {
        float acc[4][4];
        #pragma unroll
        for (int n = 0; n < 4; n++)
            #pragma unroll
            for (int q = 0; q < 4; q++) acc[n][q] = 0.f;

        const uint4* __restrict__ Wlvl = g_WdF + (size_t)lvl*9*1024;
        STAGE_D(0, 0);
        __syncthreads();
        for (int tap = 0; tap < 9; tap++) {
            int cur = tap & 1, nxt = cur ^ 1;
            if (tap < 8) STAGE_D(tap + 1, nxt);
            const unsigned* vh = Vh[cur];
            const unsigned* vl = Vl[cur];
            const uint4* Wp = Wlvl + (size_t)tap*1024 + wn*4*32 + lane;
            #pragma unroll
            for (int ks = 0; ks < 4; ks++) {
                unsigned ahi[4], alo[4];
                ldsm4(ahi, vh + lmoff + ks*8);
                ldsm4(alo, vl + lmoff + ks*8);
                #pragma unroll
                for (int nb = 0; nb < 4; nb++) {
                    uint4 wv = __ldg(Wp + (ks*8 + nb)*32);
                    unsigned bhi[2] = { wv.x, wv.y };
                    unsigned blo[2] = { wv.z, wv.w };
                    mma_bf16(acc[nb], ahi, bhi);
                    mma_bf16(acc[nb], alo, bhi);
                    mma_bf16(acc[nb], ahi, blo);
                }
            }
            __syncthreads();
        }
        // epilogue + fused SE partial reduction
        int px0 = pbase + wm*16 + l4;
        #pragma unroll
        for (int nb = 0; nb < 4; nb++) {
            int o = wn*32 + nb*8 + 2*t4;
            float b0 = dc_b[lvl*CC + o], b1 = dc_b[lvl*CC + o + 1];
            float u0 = acc[nb][0] + b0, u1 = acc[nb][1] + b1;
            float u2 = acc[nb][2] + b0, u3 = acc[nb][3] + b1;
            *(float2*)(gdc + (size_t)px0*CC + o)     = make_float2(u0, u1);
            *(float2*)(gdc + (size_t)(px0+8)*CC + o) = make_float2(u2, u3);
            float s0 = u0 + u2, s1 = u1 + u3;
            #pragma unroll
            for (int sh = 4; sh < 32; sh <<= 1) {
                s0 += __shfl_xor_sync(0xffffffffu, s0, sh);
                s1 += __shfl_xor_sync(0xffffffffu, s1, sh);
            }
            if (l4 == 0) {
                atomicAdd(&sred[o], s0);
                atomicAdd(&sred[o + 1], s1);
            }
        }
        __syncthreads();
        if (tid < 64) atomicAdd(&g_sum[lvl][b*CC + tid], sred[tid]);
    }
    #undef STAGE_P
    #undef STAGE_D

    // ============ last block computes SE gates (O(1) work, run once) ============
    __shared__ unsigned s_last;
    __threadfence();
    if (tid == 0) {
        unsigned v = atomicAdd(&g_cnt[lvl], 1u);
        s_last = (v == gridDim.x - 1u) ? 1u : 0u;
    }
    __syncthreads();
    if (s_last) {
        __shared__ float hid[16];
        float invn = 1.f / (float)hw;
        if (tid < 16) {
            int bq = tid >> 2, r = tid & 3;
            float a = se_b1[lvl*4 + r];
            #pragma unroll 8
            for (int c = 0; c < CC; c++)
                a += se_w1[(lvl*4 + r)*CC + c] * g_sum[lvl][bq*CC + c] * invn;
            hid[tid] = fmaxf(a, 0.f);
        }
        __syncthreads();
        {
            int bq = tid >> 6, c = tid & 63;
            float a = se_b2[lvl*CC + c];
            #pragma unroll
            for (int r = 0; r < 4; r++) a += se_w2[(lvl*CC + c)*4 + r] * hid[bq*4 + r];
            g_gates[lvl][bq*CC + c] = 1.f / (1.f + expf(-a));
        }
    }
}

// ---------------- 2x2 avg-pool + gate (critical path, small) ----------------
__global__ void down_k(int lvl, int h, int w, int buf)
{
    int i = blockIdx.x * 256 + threadIdx.x;
    int w2 = w >> 1, h2 = h >> 1;
    int c4 = i & 15; int p = i >> 4;
    int x = p % w2; int t = p / w2; int y = t % h2; int b = t / h2;
    float4 g = *(const float4*)(&g_gates[lvl][b*CC + 4*c4]);
    const float* base = g_dcP[buf] + (((size_t)(b*h + 2*y)*w + 2*x))*CC + 4*c4;
    float4 a0 = *(const float4*)(base);
    float4 a1 = *(const float4*)(base + CC);
    float4 a2 = *(const float4*)(base + (size_t)w*CC);
    float4 a3 = *(const float4*)(base + (size_t)w*CC + CC);
    float4 v;
    v.x = 0.25f*g.x*(a0.x + a1.x + a2.x + a3.x);
    v.y = 0.25f*g.y*(a0.y + a1.y + a2.y + a3.y);
    v.z = 0.25f*g.z*(a0.z + a1.z + a2.z + a3.z);
    v.w = 0.25f*g.w*(a0.w + a1.w + a2.w + a3.w);
    *(float4*)(g_curN + (size_t)i*4) = v;
}

// ---------------- gate + bilinear upsample to feats (side stream) ------------
__global__ void upsample_k(int lvl, int h, int w, int buf)
{
    int i = blockIdx.x * 256 + threadIdx.x;   // BB*HH*WW*16 threads
    int c4 = i & 15; int p = i >> 4;
    int X = p & 127; p >>= 7; int Y = p & 127; int b = p >> 7;
    float4 g = *(const float4*)(&g_gates[lvl][b*CC + 4*c4]);
    const float* gdc = g_dcP[buf];
    float4 v;
    if (h == HH) {
        v = *(const float4*)(gdc + ((size_t)((b*HH + Y)*WW + X))*CC + 4*c4);
    } else {
        float sc = (float)h * (1.f/128.f);
        float sy = fminf(fmaxf((Y + 0.5f)*sc - 0.5f, 0.f), (float)(h-1));
        float sx = fminf(fmaxf((X + 0.5f)*sc - 0.5f, 0.f), (float)(w-1));
        int y0 = (int)sy; int y1 = min(y0+1, h-1); float wy = sy - (float)y0;
        int x0 = (int)sx; int x1 = min(x0+1, w-1); float wx = sx - (float)x0;
        const float* base = gdc + (size_t)b*h*w*CC + 4*c4;
        float4 v00 = *(const float4*)(base + ((size_t)y0*w + x0)*CC);
        float4 v01 = *(const float4*)(base + ((size_t)y0*w + x1)*CC);
        float4 v10 = *(const float4*)(base + ((size_t)y1*w + x0)*CC);
        float4 v11 = *(const float4*)(base + ((size_t)y1*w + x1)*CC);
        float w00 = (1.f-wy)*(1.f-wx), w01 = (1.f-wy)*wx, w10 = wy*(1.f-wx), w11 = wy*wx;
        v.x = w00*v00.x + w01*v01.x + w10*v10.x + w11*v11.x;
        v.y = w00*v00.y + w01*v01.y + w10*v10.y + w11*v11.y;
        v.z = w00*v00.z + w01*v01.z + w10*v10.z + w11*v11.z;
        v.w = w00*v00.w + w01*v01.w + w10*v10.w + w11*v11.w;
    }
    v.x *= g.x; v.y *= g.y; v.z *= g.z; v.w *= g.w;
    *(float4*)(g_feats[lvl] + (size_t)i*4) = v;
}

// ---------------- fuse: cumulative 1x1 over 4 levels ----------------
__global__ void fuse_k(const float* __restrict__ fuse_b, float* __restrict__ out)
{
    __shared__ float sf[32*256];
    int pbase = blockIdx.x * 32;
    int tid = threadIdx.x;              // 256
    for (int t = tid; t < 32*256; t += 256) {
        int px = t >> 8; int jc = t & 255; int j = jc >> 6; int c = jc & 63;
        sf[t] = g_feats[j][(size_t)(pbase + px)*CC + c];
    }
    __syncthreads();
    int o = tid & 63; int pq = tid >> 6;
    float acc[8];
    #pragma unroll
    for (int q = 0; q < 8; q++) acc[q] = 0.f;
    const float4* wr = (const float4*)g_wcumT;
    #pragma unroll 4
    for (int j = 0; j < 64; j++) {
        float4 ww = wr[j*64 + o];
        #pragma unroll
        for (int q = 0; q < 8; q++) {
            float4 sv = ((const float4*)sf)[(pq*8 + q)*64 + j];
            acc[q] += ww.x*sv.x + ww.y*sv.y + ww.z*sv.z + ww.w*sv.w;
        }
    }
    float bias = fuse_b[o];
    __syncthreads();
    float* sout = sf;
    #pragma unroll
    for (int q = 0; q < 8; q++) sout[o*32 + pq*8 + q] = acc[q] + bias;
    __syncthreads();
    int X0 = pbase & 127; int r = pbase >> 7; int Y = r & 127; int b = r >> 7;
    for (int t = tid; t < 64*8; t += 256) {
        int oo = t >> 3; int q = t & 7;
        float4 v = ((const float4*)sout)[oo*8 + q];
        *(float4*)(out + (((size_t)(b*CC + oo)*HH + Y)*WW + X0 + q*4)) = v;
    }
}

// ---------------- launch ----------------
extern "C" void kernel_launch(void* const* d_in, const int* in_sizes, int n_in,
                              void* d_out, int out_size)
{
    const float* x      = (const float*)d_in[0];
    const float* off_w  = (const float*)d_in[1];
    const float* off_b  = (const float*)d_in[2];
    const float* dc_w   = (const float*)d_in[3];
    const float* dc_b   = (const float*)d_in[4];
    const float* se_w1  = (const float*)d_in[5];
    const float* se_b1  = (const float*)d_in[6];
    const float* se_w2  = (const float*)d_in[7];
    const float* se_b2  = (const float*)d_in[8];
    const float* fuse_w = (const float*)d_in[9];
    const float* fuse_b = (const float*)d_in[10];
    float* out = (float*)d_out;

    const int SMEM_F = 14976 * 4;   // 59904: V ping-pong + s_off + metadata
    static bool init_done = false;
    static cudaStream_t tS;
    static cudaEvent_t evC[LL], evU[LL];
    if (!init_done) {
        cudaFuncSetAttribute(conv_fused_k, cudaFuncAttributeMaxDynamicSharedMemorySize, SMEM_F);
        cudaStreamCreateWithFlags(&tS, cudaStreamNonBlocking);
        for (int l = 0; l < LL; l++) {
            cudaEventCreateWithFlags(&evC[l], cudaEventDisableTiming);
            cudaEventCreateWithFlags(&evU[l], cudaEventDisableTiming);
        }
        init_done = true;
    }

    prep_k<<<(LL*9*4*2*4*32 + 255)/256, 256>>>(off_w, dc_w, fuse_w);
    to_nhwc_k<<<BB*HH*4, 256>>>(x);

    for (int l = 0; l < LL; l++) {
        int h = HH >> l, w = WW >> l;
        int usex = (l == 0);
        int buf = l & 1;
        int grid = (BB*h*w)/64;
        if (l >= 2)  // same dc buffer as level l-2: wait for its upsample reads
            cudaStreamWaitEvent(0, evU[l-2], 0);
        conv_fused_k<<<grid, 256, SMEM_F>>>(off_b, dc_b, se_w1, se_b1, se_w2, se_b2,
                                            l, h, w, usex, buf);
        cudaEventRecord(evC[l], 0);
        cudaStreamWaitEvent(tS, evC[l], 0);
        upsample_k<<<(BB*HH*WW*16)/256, 256, 0, tS>>>(l, h, w, buf);
        cudaEventRecord(evU[l], tS);
        if (l < LL-1)
            down_k<<<(BB*(h>>1)*(w>>1)*16)/256, 256>>>(l, h, w, buf);
    }
    for (int l = 0; l < LL; l++)
        cudaStreamWaitEvent(0, evU[l], 0);
    fuse_k<<<(BB*HH*WW)/32, 256>>>(fuse_b, out);
}

// round 12
// speedup vs baseline: 1.0707x; 1.0707x over previous
#include <cuda_runtime.h>
#include <cuda_bf16.h>

#define BB 4
#define CC 64
#define HH 128
#define WW 128
#define LL 4
#define NOFF 18
#define SV 36   // V row stride in u32 (144B, 16B-aligned rows for ldmatrix)

// ---------------- scratch ----------------
__device__ float g_xnhwc[BB*HH*WW*CC];
__device__ float g_curN [BB*HH*WW*CC];
__device__ float g_dcP  [2][BB*HH*WW*CC];    // ping-pong deform outputs
__device__ float g_feats[LL][BB*HH*WW*CC];
__device__ float g_sum  [LL][BB*CC];
__device__ float g_gates[LL][BB*CC];
__device__ unsigned g_cnt[LL];
__device__ float g_wcumT[64*64*4];           // [j][o] float4 cumulative fuse weights
__device__ uint4 g_WdF[LL*9*1024];           // deform W fragments [(ks*8+og)*32+lane]
__device__ uint4 g_WoF[LL*9*512];            // offset W fragments [(ks*4+og)*32+lane]

// Dekker split of 2 floats into bf16x2 hi + bf16x2 lo (exact residual)
__device__ __forceinline__ void split2(float v0, float v1, unsigned& hi, unsigned& lo) {
    unsigned h;
    asm("cvt.rn.bf16x2.f32 %0, %1, %2;" : "=r"(h) : "f"(v1), "f"(v0));
    float h0 = __uint_as_float(h << 16);
    float h1 = __uint_as_float(h & 0xffff0000u);
    float r0 = v0 - h0, r1 = v1 - h1;
    unsigned l;
    asm("cvt.rn.bf16x2.f32 %0, %1, %2;" : "=r"(l) : "f"(r1), "f"(r0));
    hi = h; lo = l;
}

__device__ __forceinline__ void mma_bf16(float c[4], const unsigned a[4], const unsigned b[2]) {
    asm volatile("mma.sync.aligned.m16n8k16.row.col.f32.bf16.bf16.f32 "
        "{%0,%1,%2,%3}, {%4,%5,%6,%7}, {%8,%9}, {%0,%1,%2,%3};"
        : "+f"(c[0]), "+f"(c[1]), "+f"(c[2]), "+f"(c[3])
        : "r"(a[0]), "r"(a[1]), "r"(a[2]), "r"(a[3]), "r"(b[0]), "r"(b[1]));
}
__device__ __forceinline__ void ldsm4(unsigned r[4], const unsigned* ptr) {
    unsigned addr = (unsigned)__cvta_generic_to_shared(ptr);
    asm volatile("ldmatrix.sync.aligned.m8n8.x4.shared.b16 {%0,%1,%2,%3}, [%4];"
        : "=r"(r[0]), "=r"(r[1]), "=r"(r[2]), "=r"(r[3]) : "r"(addr));
}

// ---------------- prep: fragment-ordered weights + cumulative fuse ----------
__global__ void prep_k(const float* __restrict__ off_w,
                       const float* __restrict__ dc_w,
                       const float* __restrict__ fuse_w)
{
    int i = blockIdx.x * blockDim.x + threadIdx.x;
    if (i < LL*9*4*8*32) {              // deform fragments: (l,tap,ks,og,lane)
        int lane = i & 31; int r = i >> 5;
        int og = r & 7; r >>= 3;
        int ks = r & 3; r >>= 2; int tap = r % 9; int l = r / 9;
        int t4 = lane & 3, l4 = lane >> 2;
        int o = og*8 + l4;
        int c2a = ks*8 + t4, c2b = c2a + 4;
        float va0 = dc_w[((l*CC + o)*CC + 2*c2a)*9 + tap];
        float va1 = dc_w[((l*CC + o)*CC + 2*c2a + 1)*9 + tap];
        float vb0 = dc_w[((l*CC + o)*CC + 2*c2b)*9 + tap];
        float vb1 = dc_w[((l*CC + o)*CC + 2*c2b + 1)*9 + tap];
        unsigned ha, la, hb, lb;
        split2(va0, va1, ha, la); split2(vb0, vb1, hb, lb);
        g_WdF[(size_t)(l*9 + tap)*1024 + (ks*8 + og)*32 + lane] = make_uint4(ha, hb, la, lb);
    }
    if (i < LL*9*4*4*32) {              // offset fragments: (l,tap,ks,og,lane)
        int lane = i & 31; int r = i >> 5;
        int og = r & 3; r >>= 2;
        int ks = r & 3; r >>= 2; int tap = r % 9; int l = r / 9;
        int t4 = lane & 3, l4 = lane >> 2;
        int o = og*8 + l4;
        int c2a = ks*8 + t4, c2b = c2a + 4;
        float va0 = 0.f, va1 = 0.f, vb0 = 0.f, vb1 = 0.f;
        if (o < NOFF) {
            va0 = off_w[((l*NOFF + o)*CC + 2*c2a)*9 + tap];
            va1 = off_w[((l*NOFF + o)*CC + 2*c2a + 1)*9 + tap];
            vb0 = off_w[((l*NOFF + o)*CC + 2*c2b)*9 + tap];
            vb1 = off_w[((l*NOFF + o)*CC + 2*c2b + 1)*9 + tap];
        }
        unsigned ha, la, hb, lb;
        split2(va0, va1, ha, la); split2(vb0, vb1, hb, lb);
        g_WoF[(size_t)(l*9 + tap)*512 + (ks*4 + og)*32 + lane] = make_uint4(ha, hb, la, lb);
    }
    if (i < 64*64*4) {                  // wcumT[(j*64+o)*4+t]
        int t = i & 3; int o = (i >> 2) & 63; int j = i >> 8;
        int e = j*4 + t; int lev = e >> 6; int c = e & 63;
        float s = 0.f;
        for (int u = 0; u <= lev; u++) s += fuse_w[o*(LL*CC) + u*CC + c];
        g_wcumT[i] = s;
    }
    if (i < LL*BB*CC) ((float*)g_sum)[i] = 0.f;
    if (i < LL) g_cnt[i] = 0u;
}

// ---------------- NCHW -> NHWC (smem-tiled transpose) ----------------
__global__ void to_nhwc_k(const float* __restrict__ x)
{
    __shared__ float t[64][33];
    int blk = blockIdx.x;
    int xt = blk & 3; int r = blk >> 2; int y = r & 127; int b = r >> 7;
    int x0 = xt * 32;
    int tid = threadIdx.x;              // 256
    int xx = tid & 31, cg = tid >> 5;
    #pragma unroll
    for (int pass = 0; pass < 8; pass++) {
        int c = pass*8 + cg;
        t[c][xx] = x[((size_t)(b*CC + c)*HH + y)*WW + x0 + xx];
    }
    __syncthreads();
    int c = tid & 63, xg = tid >> 6;
    #pragma unroll
    for (int pass = 0; pass < 8; pass++) {
        int xo = pass*4 + xg;
        g_xnhwc[((size_t)((b*HH + y)*WW) + x0 + xo)*CC + c] = t[c][xo];
    }
}

// ---------------- FUSED offset-conv + deform-conv, MP px/block ---------------
// MP = 64 (4 m-warps x 2 n-groups) or 32 (2 m-warps x 4 n-groups).
template<int MP>
__global__ void __launch_bounds__(256, 3) conv_fused_k(
    const float* __restrict__ off_b, const float* __restrict__ dc_b,
    const float* __restrict__ se_w1, const float* __restrict__ se_b1,
    const float* __restrict__ se_w2, const float* __restrict__ se_b2,
    int lvl, int h, int w, int use_x, int buf)
{
    constexpr int MPW   = MP/16;           // warps along m
    constexpr int NBd   = MPW;             // deform n-blocks per warp
    constexpr int NBo   = MPW/2;           // offset n-blocks per warp (>=1)
    constexpr int NSTEP = MP/16;           // staging steps
    constexpr int WSH   = (MPW == 4) ? 2 : 1;

    extern __shared__ unsigned smem[];
    unsigned* Vh[2] = { smem, smem + 2304 };
    unsigned* Vl[2] = { smem + 4608, smem + 6912 };
    float*  s_offm = (float*)(smem + 9216);    // [64][18]
    int*    s_po   = (int*)(smem + 10368);     // 576 ints  (phase 1, overlaps s_mo4)
    int4*   s_mo4  = (int4*)(smem + 10368);    // 576 int4  (phase 2)
    float4* s_mw4  = (float4*)(smem + 12672);  // 576 float4
    __shared__ float sred[64];

    int tid = threadIdx.x;
    int lane = tid & 31, warp = tid >> 5;
    int wm = warp & (MPW-1), wn = warp >> WSH;
    int t4 = lane & 3, l4 = lane >> 2;
    int pbase = blockIdx.x * MP;
    const float* src = use_x ? g_xnhwc : g_curN;
    float* gdc = g_dcP[buf];
    int hw = h * w;
    int b = pbase / hw;
    const float* sb0 = src + (size_t)b*hw*CC;
    int c4 = lane & 15, pxo = lane >> 4;

    if (tid < 64) sred[tid] = 0.f;

    unsigned lmoff = (unsigned)((wm*16 + (lane & 15))*SV + (lane >> 4)*4);

    // phase-1 metadata: per (px,tap) patch offset (or -1)
    for (int t = tid; t < MP*9; t += 256) {
        int px = t / 9, k = t - px*9;
        int p = pbase + px;
        int x = p % w; int y = (p / w) % h;
        int yy = y + k/3 - 1, xx = x + k%3 - 1;
        s_po[t] = ((unsigned)yy < (unsigned)h && (unsigned)xx < (unsigned)w)
                    ? (yy*w + xx)*CC : -1;
    }
    __syncthreads();

    #define STAGE_P(tap_, buf_) {                                                 \
        for (int step = 0; step < NSTEP; step++) {                                \
            int px = step*16 + warp*2 + pxo;                                      \
            int o = s_po[px*9 + (tap_)];                                          \
            float v0 = 0.f, v1 = 0.f, v2 = 0.f, v3 = 0.f;                         \
            if (o >= 0) {                                                         \
                float4 q = *(const float4*)(sb0 + o + 4*c4);                      \
                v0 = q.x; v1 = q.y; v2 = q.z; v3 = q.w;                           \
            }                                                                     \
            unsigned h0, l0, h1, l1;                                              \
            split2(v0, v1, h0, l0); split2(v2, v3, h1, l1);                       \
            *(uint2*)&Vh[buf_][px*SV + 2*c4] = make_uint2(h0, h1);                \
            *(uint2*)&Vl[buf_][px*SV + 2*c4] = make_uint2(l0, l1);                \
        }                                                                         \
    }
    #define STAGE_D(tap_, buf_) {                                                 \
        for (int step = 0; step < NSTEP; step++) {                                \
            int px = step*16 + warp*2 + pxo;                                      \
            int mt = px*9 + (tap_);                                               \
            int4 mo = s_mo4[mt]; float4 mw = s_mw4[mt];                           \
            const float* sb = sb0 + 4*c4;                                         \
            float v0 = 0.f, v1 = 0.f, v2 = 0.f, v3 = 0.f;                         \
            if (mo.x >= 0) { float4 q = *(const float4*)(sb + mo.x); v0 += mw.x*q.x; v1 += mw.x*q.y; v2 += mw.x*q.z; v3 += mw.x*q.w; } \
            if (mo.y >= 0) { float4 q = *(const float4*)(sb + mo.y); v0 += mw.y*q.x; v1 += mw.y*q.y; v2 += mw.y*q.z; v3 += mw.y*q.w; } \
            if (mo.z >= 0) { float4 q = *(const float4*)(sb + mo.z); v0 += mw.z*q.x; v1 += mw.z*q.y; v2 += mw.z*q.z; v3 += mw.z*q.w; } \
            if (mo.w >= 0) { float4 q = *(const float4*)(sb + mo.w); v0 += mw.w*q.x; v1 += mw.w*q.y; v2 += mw.w*q.z; v3 += mw.w*q.w; } \
            unsigned h0, l0, h1, l1;                                              \
            split2(v0, v1, h0, l0); split2(v2, v3, h1, l1);                       \
            *(uint2*)&Vh[buf_][px*SV + 2*c4] = make_uint2(h0, h1);                \
            *(uint2*)&Vl[buf_][px*SV + 2*c4] = make_uint2(l0, l1);                \
        }                                                                         \
    }

    // ============ PHASE 1: offset conv ============
    {
        float acc[NBo][4];
        #pragma unroll
        for (int n = 0; n < NBo; n++)
            #pragma unroll
            for (int q = 0; q < 4; q++) acc[n][q] = 0.f;

        const uint4* __restrict__ Wlvl = g_WoF + (size_t)lvl*9*512;
        STAGE_P(0, 0);
        __syncthreads();
        for (int tap = 0; tap < 9; tap++) {
            int cur = tap & 1, nxt = cur ^ 1;
            if (tap < 8) STAGE_P(tap + 1, nxt);
            const unsigned* vh = Vh[cur];
            const unsigned* vl = Vl[cur];
            const uint4* Wp = Wlvl + (size_t)tap*512 + (wn*NBo)*32 + lane;
            #pragma unroll
            for (int ks = 0; ks < 4; ks++) {
                unsigned ahi[4], alo[4];
                ldsm4(ahi, vh + lmoff + ks*8);
                ldsm4(alo, vl + lmoff + ks*8);
                #pragma unroll
                for (int nb = 0; nb < NBo; nb++) {
                    uint4 wv = __ldg(Wp + (ks*4 + nb)*32);
                    unsigned bhi[2] = { wv.x, wv.y };
                    unsigned blo[2] = { wv.z, wv.w };
                    mma_bf16(acc[nb], ahi, bhi);
                    mma_bf16(acc[nb], alo, bhi);
                    mma_bf16(acc[nb], ahi, blo);
                }
            }
            __syncthreads();
        }
        // write offsets to smem
        int px0l = wm*16 + l4;
        #pragma unroll
        for (int nb = 0; nb < NBo; nb++) {
            int o = (wn*NBo + nb)*8 + 2*t4;
            if (o < NOFF) {
                float b0 = off_b[lvl*NOFF + o];
                s_offm[px0l*18 + o]     = acc[nb][0] + b0;
                s_offm[(px0l+8)*18 + o] = acc[nb][2] + b0;
            }
            if (o + 1 < NOFF) {
                float b1 = off_b[lvl*NOFF + o + 1];
                s_offm[px0l*18 + o + 1]     = acc[nb][1] + b1;
                s_offm[(px0l+8)*18 + o + 1] = acc[nb][3] + b1;
            }
        }
        __syncthreads();
    }

    // ============ phase-2 metadata: corner offsets + bilinear weights ============
    for (int t = tid; t < MP*9; t += 256) {
        int px = t / 9, k = t - px*9;
        int p = pbase + px;
        int x = p % w; int y = (p / w) % h;
        float dy = s_offm[px*18 + 2*k];
        float dx = s_offm[px*18 + 2*k + 1];
        float py  = (float)(y + k/3 - 1) + dy;
        float pxx = (float)(x + k%3 - 1) + dx;
        float y0f = floorf(py), x0f = floorf(pxx);
        int y0 = (int)y0f, x0 = (int)x0f;
        float wy = py - y0f, wx = pxx - x0f;
        bool yi0 = (unsigned)y0       < (unsigned)h;
        bool yi1 = (unsigned)(y0 + 1) < (unsigned)h;
        bool xi0 = (unsigned)x0       < (unsigned)w;
        bool xi1 = (unsigned)(x0 + 1) < (unsigned)w;
        int4 mo; float4 mw;
        mo.x = (yi0 && xi0) ? (y0*w + x0)*CC       : -1;  mw.x = (1.f-wy)*(1.f-wx);
        mo.y = (yi0 && xi1) ? (y0*w + x0 + 1)*CC   : -1;  mw.y = (1.f-wy)*wx;
        mo.z = (yi1 && xi0) ? ((y0+1)*w + x0)*CC   : -1;  mw.z = wy*(1.f-wx);
        mo.w = (yi1 && xi1) ? ((y0+1)*w + x0+1)*CC : -1;  mw.w = wy*wx;
        s_mo4[t] = mo; s_mw4[t] = mw;
    }
    __syncthreads();

    // ============ PHASE 2: deform conv ============
    {
        float acc[NBd][4];
        #pragma unroll
        for (int n = 0; n < NBd; n++)
            #pragma unroll
            for (int q = 0; q < 4; q++) acc[n][q] = 0.f;

        const uint4* __restrict__ Wlvl = g_WdF + (size_t)lvl*9*1024;
        STAGE_D(0, 0);
        __syncthreads();
        for (int tap = 0; tap < 9; tap++) {
            int cur = tap & 1, nxt = cur ^ 1;
            if (tap < 8) STAGE_D(tap + 1, nxt);
            const unsigned* vh = Vh[cur];
            const unsigned* vl = Vl[cur];
            const uint4* Wp = Wlvl + (size_t)tap*1024 + (wn*NBd)*32 + lane;
            #pragma unroll
            for (int ks = 0; ks < 4; ks++) {
                unsigned ahi[4], alo[4];
                ldsm4(ahi, vh + lmoff + ks*8);
                ldsm4(alo, vl + lmoff + ks*8);
                #pragma unroll
                for (int nb = 0; nb < NBd; nb++) {
                    uint4 wv = __ldg(Wp + (ks*8 + nb)*32);
                    unsigned bhi[2] = { wv.x, wv.y };
                    unsigned blo[2] = { wv.z, wv.w };
                    mma_bf16(acc[nb], ahi, bhi);
                    mma_bf16(acc[nb], alo, bhi);
                    mma_bf16(acc[nb], ahi, blo);
                }
            }
            __syncthreads();
        }
        // epilogue + fused SE partial reduction
        int px0 = pbase + wm*16 + l4;
        #pragma unroll
        for (int nb = 0; nb < NBd; nb++) {
            int o = (wn*NBd + nb)*8 + 2*t4;
            float b0 = dc_b[lvl*CC + o], b1 = dc_b[lvl*CC + o + 1];
            float u0 = acc[nb][0] + b0, u1 = acc[nb][1] + b1;
            float u2 = acc[nb][2] + b0, u3 = acc[nb][3] + b1;
            *(float2*)(gdc + (size_t)px0*CC + o)     = make_float2(u0, u1);
            *(float2*)(gdc + (size_t)(px0+8)*CC + o) = make_float2(u2, u3);
            float s0 = u0 + u2, s1 = u1 + u3;
            #pragma unroll
            for (int sh = 4; sh < 32; sh <<= 1) {
                s0 += __shfl_xor_sync(0xffffffffu, s0, sh);
                s1 += __shfl_xor_sync(0xffffffffu, s1, sh);
            }
            if (l4 == 0) {
                atomicAdd(&sred[o], s0);
                atomicAdd(&sred[o + 1], s1);
            }
        }
        __syncthreads();
        if (tid < 64) atomicAdd(&g_sum[lvl][b*CC + tid], sred[tid]);
    }
    #undef STAGE_P
    #undef STAGE_D

    // ============ last block computes SE gates (O(1) work, run once) ============
    __shared__ unsigned s_last;
    __threadfence();
    if (tid == 0) {
        unsigned v = atomicAdd(&g_cnt[lvl], 1u);
        s_last = (v == gridDim.x - 1u) ? 1u : 0u;
    }
    __syncthreads();
    if (s_last) {
        __shared__ float hid[16];
        float invn = 1.f / (float)hw;
        if (tid < 16) {
            int bq = tid >> 2, r = tid & 3;
            float a = se_b1[lvl*4 + r];
            #pragma unroll 8
            for (int c = 0; c < CC; c++)
                a += se_w1[(lvl*4 + r)*CC + c] * g_sum[lvl][bq*CC + c] * invn;
            hid[tid] = fmaxf(a, 0.f);
        }
        __syncthreads();
        {
            int bq = tid >> 6, c = tid & 63;
            float a = se_b2[lvl*CC + c];
            #pragma unroll
            for (int r = 0; r < 4; r++) a += se_w2[(lvl*CC + c)*4 + r] * hid[bq*4 + r];
            g_gates[lvl][bq*CC + c] = 1.f / (1.f + expf(-a));
        }
    }
}

// ---------------- 2x2 avg-pool + gate (critical path, small) ----------------
__global__ void down_k(int lvl, int h, int w, int buf)
{
    int i = blockIdx.x * 256 + threadIdx.x;
    int w2 = w >> 1, h2 = h >> 1;
    int c4 = i & 15; int p = i >> 4;
    int x = p % w2; int t = p / w2; int y = t % h2; int b = t / h2;
    float4 g = *(const float4*)(&g_gates[lvl][b*CC + 4*c4]);
    const float* base = g_dcP[buf] + (((size_t)(b*h + 2*y)*w + 2*x))*CC + 4*c4;
    float4 a0 = *(const float4*)(base);
    float4 a1 = *(const float4*)(base + CC);
    float4 a2 = *(const float4*)(base + (size_t)w*CC);
    float4 a3 = *(const float4*)(base + (size_t)w*CC + CC);
    float4 v;
    v.x = 0.25f*g.x*(a0.x + a1.x + a2.x + a3.x);
    v.y = 0.25f*g.y*(a0.y + a1.y + a2.y + a3.y);
    v.z = 0.25f*g.z*(a0.z + a1.z + a2.z + a3.z);
    v.w = 0.25f*g.w*(a0.w + a1.w + a2.w + a3.w);
    *(float4*)(g_curN + (size_t)i*4) = v;
}

// ---------------- gate + bilinear upsample to feats (side stream) ------------
__global__ void upsample_k(int lvl, int h, int w, int buf)
{
    int i = blockIdx.x * 256 + threadIdx.x;   // BB*HH*WW*16 threads
    int c4 = i & 15; int p = i >> 4;
    int X = p & 127; p >>= 7; int Y = p & 127; int b = p >> 7;
    float4 g = *(const float4*)(&g_gates[lvl][b*CC + 4*c4]);
    const float* gdc = g_dcP[buf];
    float4 v;
    if (h == HH) {
        v = *(const float4*)(gdc + ((size_t)((b*HH + Y)*WW + X))*CC + 4*c4);
    } else {
        float sc = (float)h * (1.f/128.f);
        float sy = fminf(fmaxf((Y + 0.5f)*sc - 0.5f, 0.f), (float)(h-1));
        float sx = fminf(fmaxf((X + 0.5f)*sc - 0.5f, 0.f), (float)(w-1));
        int y0 = (int)sy; int y1 = min(y0+1, h-1); float wy = sy - (float)y0;
        int x0 = (int)sx; int x1 = min(x0+1, w-1); float wx = sx - (float)x0;
        const float* base = gdc + (size_t)b*h*w*CC + 4*c4;
        float4 v00 = *(const float4*)(base + ((size_t)y0*w + x0)*CC);
        float4 v01 = *(const float4*)(base + ((size_t)y0*w + x1)*CC);
        float4 v10 = *(const float4*)(base + ((size_t)y1*w + x0)*CC);
        float4 v11 = *(const float4*)(base + ((size_t)y1*w + x1)*CC);
        float w00 = (1.f-wy)*(1.f-wx), w01 = (1.f-wy)*wx, w10 = wy*(1.f-wx), w11 = wy*wx;
        v.x = w00*v00.x + w01*v01.x + w10*v10.x + w11*v11.x;
        v.y = w00*v00.y + w01*v01.y + w10*v10.y + w11*v11.y;
        v.z = w00*v00.z + w01*v01.z + w10*v10.z + w11*v11.z;
        v.w = w00*v00.w + w01*v01.w + w10*v10.w + w11*v11.w;
    }
    v.x *= g.x; v.y *= g.y; v.z *= g.z; v.w *= g.w;
    *(float4*)(g_feats[lvl] + (size_t)i*4) = v;
}

// ---------------- fuse: cumulative 1x1 over 4 levels ----------------
__global__ void fuse_k(const float* __restrict__ fuse_b, float* __restrict__ out)
{
    __shared__ float sf[32*256];
    int pbase = blockIdx.x * 32;
    int tid = threadIdx.x;              // 256
    for (int t = tid; t < 32*256; t += 256) {
        int px = t >> 8; int jc = t & 255; int j = jc >> 6; int c = jc & 63;
        sf[t] = g_feats[j][(size_t)(pbase + px)*CC + c];
    }
    __syncthreads();
    int o = tid & 63; int pq = tid >> 6;
    float acc[8];
    #pragma unroll
    for (int q = 0; q < 8; q++) acc[q] = 0.f;
    const float4* wr = (const float4*)g_wcumT;
    #pragma unroll 4
    for (int j = 0; j < 64; j++) {
        float4 ww = wr[j*64 + o];
        #pragma unroll
        for (int q = 0; q < 8; q++) {
            float4 sv = ((const float4*)sf)[(pq*8 + q)*64 + j];
            acc[q] += ww.x*sv.x + ww.y*sv.y + ww.z*sv.z + ww.w*sv.w;
        }
    }
    float bias = fuse_b[o];
    __syncthreads();
    float* sout = sf;
    #pragma unroll
    for (int q = 0; q < 8; q++) sout[o*32 + pq*8 + q] = acc[q] + bias;
    __syncthreads();
    int X0 = pbase & 127; int r = pbase >> 7; int Y = r & 127; int b = r >> 7;
    for (int t = tid; t < 64*8; t += 256) {
        int oo = t >> 3; int q = t & 7;
        float4 v = ((const float4*)sout)[oo*8 + q];
        *(float4*)(out + (((size_t)(b*CC + oo)*HH + Y)*WW + X0 + q*4)) = v;
    }
}

// ---------------- launch ----------------
extern "C" void kernel_launch(void* const* d_in, const int* in_sizes, int n_in,
                              void* d_out, int out_size)
{
    const float* x      = (const float*)d_in[0];
    const float* off_w  = (const float*)d_in[1];
    const float* off_b  = (const float*)d_in[2];
    const float* dc_w   = (const float*)d_in[3];
    const float* dc_b   = (const float*)d_in[4];
    const float* se_w1  = (const float*)d_in[5];
    const float* se_b1  = (const float*)d_in[6];
    const float* se_w2  = (const float*)d_in[7];
    const float* se_b2  = (const float*)d_in[8];
    const float* fuse_w = (const float*)d_in[9];
    const float* fuse_b = (const float*)d_in[10];
    float* out = (float*)d_out;

    const int SMEM_F = 14976 * 4;   // 59904
    static bool init_done = false;
    static cudaStream_t tS;
    static cudaEvent_t evC[LL], evU[LL];
    if (!init_done) {
        cudaFuncSetAttribute(conv_fused_k<64>, cudaFuncAttributeMaxDynamicSharedMemorySize, SMEM_F);
        cudaFuncSetAttribute(conv_fused_k<32>, cudaFuncAttributeMaxDynamicSharedMemorySize, SMEM_F);
        cudaStreamCreateWithFlags(&tS, cudaStreamNonBlocking);
        for (int l = 0; l < LL; l++) {
            cudaEventCreateWithFlags(&evC[l], cudaEventDisableTiming);
            cudaEventCreateWithFlags(&evU[l], cudaEventDisableTiming);
        }
        init_done = true;
    }

    prep_k<<<(LL*9*4*8*32 + 255)/256, 256>>>(off_w, dc_w, fuse_w);
    to_nhwc_k<<<BB*HH*4, 256>>>(x);

    for (int l = 0; l < LL; l++) {
        int h = HH >> l, w = WW >> l;
        int usex = (l == 0);
        int buf = l & 1;
        if (l >= 2)  // same dc buffer as level l-2: wait for its upsample reads
            cudaStreamWaitEvent(0, evU[l-2], 0);
        if (l < 2) {
            conv_fused_k<64><<<(BB*h*w)/64, 256, SMEM_F>>>(off_b, dc_b, se_w1, se_b1,
                                                           se_w2, se_b2, l, h, w, usex, buf);
        } else {
            conv_fused_k<32><<<(BB*h*w)/32, 256, SMEM_F>>>(off_b, dc_b, se_w1, se_b1,
                                                           se_w2, se_b2, l, h, w, usex, buf);
        }
        cudaEventRecord(evC[l], 0);
        cudaStreamWaitEvent(tS, evC[l], 0);
        upsample_k<<<(BB*HH*WW*16)/256, 256, 0, tS>>>(l, h, w, buf);
        cudaEventRecord(evU[l], tS);
        if (l < LL-1)
            down_k<<<(BB*(h>>1)*(w>>1)*16)/256, 256>>>(l, h, w, buf);
    }
    for (int l = 0; l < LL; l++)
        cudaStreamWaitEvent(0, evU[l], 0);
    fuse_k<<<(BB*HH*WW)/32, 256>>>(fuse_b, out);
}